// round 8
// baseline (speedup 1.0000x reference)
#include <cuda_runtime.h>

// RankDPO loss, B=8192, K=64. Single fused kernel — plain scalar f32 loop
// (f32x2 asm removed: it generated heavy MOV/register-pairing traffic).
// Facts used:
//  * delta = (g_i-g_j)*(d_i-d_j) >= 0 always (both factors monotone in r).
//  * softplus(-x) = softplus(x) - x -> wrapped pairs handled by a predicated
//    correction accumulator, off the MUFU critical path.
// Pair scheme: lane l owns (l, l+32); iter k=1..31 does A=(l,l+k) and
// B=(l+32,(l+32+k)&63) from one LDS.128 + one LDS.64 via interleaved tables:
//   P[m] = {sL[m], sL[(m+32)&63], g[m], g[(m+32)&63]},  Q[m] = {d[m], d[(m+32)&63]}
// with sL = s*log2(e); softplus in lg2 domain, one ln2 scale at the end.

#define ROWS_PER_BLOCK 8
#define THREADS 256
#define NUM_BLOCKS 1024                      // 8192 / 8
#define INV_PAIR_COUNT (1.0f / 16515072.0f)  // 8192 * 2016
#define LOG2E 1.4426950408889634f
#define LN2   0.6931471805599453f

static __device__ float g_partials[NUM_BLOCKS];
static __device__ unsigned int g_ticket = 0;

static __device__ __forceinline__ float ex2f(float x) {
    float y; asm("ex2.approx.f32 %0, %1;" : "=f"(y) : "f"(x)); return y;
}
static __device__ __forceinline__ float lg2f(float x) {
    float y; asm("lg2.approx.f32 %0, %1;" : "=f"(y) : "f"(x)); return y;
}

__global__ __launch_bounds__(THREADS)
void rankdpo_fused(const float* __restrict__ S,
                   const float* __restrict__ R,
                   float* __restrict__ out) {
    __shared__ __align__(16) float4 Ptab[ROWS_PER_BLOCK][64];
    __shared__ __align__(8)  float2 Qtab[ROWS_PER_BLOCK][64];
    __shared__ __align__(16) float  rsh[ROWS_PER_BLOCK][64];
    __shared__ float wsum[ROWS_PER_BLOCK];
    __shared__ float red[THREADS];
    __shared__ int   isLast;

    const int warp = threadIdx.x >> 5;
    const int lane = threadIdx.x & 31;
    const int row  = blockIdx.x * ROWS_PER_BLOCK + warp;

    const float* srow = S + row * 64;
    const float* rrow = R + row * 64;
    const float s0 = srow[lane];
    const float s1 = srow[lane + 32];
    const float r0 = rrow[lane];
    const float r1 = rrow[lane + 32];

    float* rw = rsh[warp];
    rw[lane]      = r0;
    rw[lane + 32] = r1;
    __syncwarp();

    // ---- rank: count strictly-greater rewards (ties ~2^-23/pair; tied pairs
    //      have dg=0 -> delta=0, so dropped tie-break is harmless) ----
    int c0 = 0, c1 = 0;
    const float4* rv = (const float4*)rw;
    #pragma unroll
    for (int q = 0; q < 16; q++) {
        const float4 v = rv[q];
        c0 += (v.x > r0) + (v.y > r0) + (v.z > r0) + (v.w > r0);
        c1 += (v.x > r1) + (v.y > r1) + (v.z > r1) + (v.w > r1);
    }
    const float d0 = __fdividef(1.f, __logf((float)(c0 + 2)));
    const float d1 = __fdividef(1.f, __logf((float)(c1 + 2)));
    const float g0 = 2.f * r0 - 1.f;
    const float g1 = 2.f * r1 - 1.f;
    const float sL0 = s0 * LOG2E;   // lg2-domain score
    const float sL1 = s1 * LOG2E;

    // interleaved tables: entry m serves pair (m,.) and the (m+32)-side pair
    Ptab[warp][lane]      = make_float4(sL0, sL1, g0, g1);
    Ptab[warp][lane + 32] = make_float4(sL1, sL0, g1, g0);
    Qtab[warp][lane]      = make_float2(d0, d1);
    Qtab[warp][lane + 32] = make_float2(d1, d0);
    __syncwarp();

    const float4* Pb = &Ptab[warp][lane];
    const float2* Qb = &Qtab[warp][lane];

    float acc0 = 0.f;   // pair-A softplus_lg2 terms
    float acc1 = 0.f;   // pair-B unoriented softplus_lg2 terms
    float accC = 0.f;   // pair-B wrapped correction: sum delta*x (lg2 domain)
    #pragma unroll
    for (int k = 1; k < 32; k++) {
        const float4 A = Pb[k];   // {sL[m], sL[(m+32)&63], g[m], g[(m+32)&63]}
        const float2 D = Qb[k];   // {d[m], d[(m+32)&63]}

        const float xA  = A.x - sL0;
        const float xB  = A.y - sL1;
        const float dtA = (A.z - g0) * (D.x - d0);   // >= 0, no abs needed
        const float dtB = (A.w - g1) * (D.y - d1);   // >= 0

        // pair A: partner index lane+k > lane always -> oriented as-is
        const float lA = lg2f(1.f + ex2f(xA));
        acc0 = fmaf(dtA, lA, acc0);

        // pair B: unoriented softplus; wrapped (lane+k>=32 -> partner < own):
        // oriented value = lB - xB, folded via correction accumulator
        const float lB = lg2f(1.f + ex2f(xB));
        acc1 = fmaf(dtB, lB, acc1);
        if (lane + k >= 32) accC = fmaf(dtB, xB, accC);
    }
    {   // gap-32 pair (lane, lane+32): i = lane+32 > j = lane
        const float delta = (g1 - g0) * (d1 - d0);   // >= 0
        acc0 = fmaf(delta, lg2f(1.f + ex2f(sL1 - sL0)), acc0);
    }
    float acc = (acc0 + acc1 - accC) * LN2;

    // ---- warp reduce ----
    #pragma unroll
    for (int o = 16; o; o >>= 1)
        acc += __shfl_xor_sync(0xffffffffu, acc, o);
    if (lane == 0) wsum[warp] = acc;
    __syncthreads();

    if (threadIdx.x == 0) {
        float s = 0.f;
        #pragma unroll
        for (int w = 0; w < ROWS_PER_BLOCK; w++) s += wsum[w];
        g_partials[blockIdx.x] = s;
        __threadfence();
        const unsigned tk = atomicAdd(&g_ticket, 1u);
        isLast = (tk == (unsigned)(gridDim.x - 1));
    }
    __syncthreads();

    // ---- last block: deterministic fixed-order reduction of 1024 partials ----
    if (isLast) {
        const int tid = threadIdx.x;
        float v = g_partials[tid]
                + g_partials[tid + 256]
                + g_partials[tid + 512]
                + g_partials[tid + 768];
        red[tid] = v;
        __syncthreads();
        #pragma unroll
        for (int stride = THREADS / 2; stride > 0; stride >>= 1) {
            if (tid < stride) red[tid] += red[tid + stride];
            __syncthreads();
        }
        if (tid == 0) {
            out[0] = red[0] * INV_PAIR_COUNT;
            g_ticket = 0;   // reset for graph replay
        }
    }
}

extern "C" void kernel_launch(void* const* d_in, const int* in_sizes, int n_in,
                              void* d_out, int out_size) {
    (void)in_sizes; (void)n_in; (void)out_size;
    const float* s = (const float*)d_in[0];   // policy_logps
    const float* r = (const float*)d_in[1];   // reward_scores
    rankdpo_fused<<<NUM_BLOCKS, THREADS>>>(s, r, (float*)d_out);
}

// round 9
// speedup vs baseline: 1.0017x; 1.0017x over previous
#include <cuda_runtime.h>

// RankDPO loss, B=8192, K=64. Single fused kernel.
// R9: pair loop MANUALLY unrolled via macro with literal k — guarantees
// immediate-offset LDS, no branches, no loop counter, static predicates.
// (All prior rounds compiled to a ROLLED loop: regs=32 tell-tale.)
// Math: delta = (g_i-g_j)*(d_i-d_j) >= 0 (monotone in r, no abs);
// softplus in lg2 domain; wrapped pair-B orientation via correction
// accumulator using softplus(-x) = softplus(x) - x.

#define ROWS_PER_BLOCK 8
#define THREADS 256
#define NUM_BLOCKS 1024                      // 8192 / 8
#define INV_PAIR_COUNT (1.0f / 16515072.0f)  // 8192 * 2016
#define LOG2E 1.4426950408889634f
#define LN2   0.6931471805599453f

static __device__ float g_partials[NUM_BLOCKS];
static __device__ unsigned int g_ticket = 0;

static __device__ __forceinline__ float ex2f(float x) {
    float y; asm("ex2.approx.f32 %0, %1;" : "=f"(y) : "f"(x)); return y;
}
static __device__ __forceinline__ float lg2f(float x) {
    float y; asm("lg2.approx.f32 %0, %1;" : "=f"(y) : "f"(x)); return y;
}

__global__ __launch_bounds__(THREADS)
void rankdpo_fused(const float* __restrict__ S,
                   const float* __restrict__ R,
                   float* __restrict__ out) {
    __shared__ __align__(16) float4 Ptab[ROWS_PER_BLOCK][64];
    __shared__ __align__(8)  float2 Qtab[ROWS_PER_BLOCK][64];
    __shared__ __align__(16) float  rsh[ROWS_PER_BLOCK][64];
    __shared__ float wsum[ROWS_PER_BLOCK];
    __shared__ float red[THREADS];
    __shared__ int   isLast;

    const int warp = threadIdx.x >> 5;
    const int lane = threadIdx.x & 31;
    const int row  = blockIdx.x * ROWS_PER_BLOCK + warp;

    const float* srow = S + row * 64;
    const float* rrow = R + row * 64;
    const float s0 = srow[lane];
    const float s1 = srow[lane + 32];
    const float r0 = rrow[lane];
    const float r1 = rrow[lane + 32];

    float* rw = rsh[warp];
    rw[lane]      = r0;
    rw[lane + 32] = r1;
    __syncwarp();

    // ---- rank: count strictly-greater rewards (ties ~2^-23/pair; tied pairs
    //      have dg=0 -> delta=0, so dropped tie-break is harmless) ----
    int c0 = 0, c1 = 0;
    const float4* rv = (const float4*)rw;
    #pragma unroll
    for (int q = 0; q < 16; q++) {
        const float4 v = rv[q];
        c0 += (v.x > r0) + (v.y > r0) + (v.z > r0) + (v.w > r0);
        c1 += (v.x > r1) + (v.y > r1) + (v.z > r1) + (v.w > r1);
    }
    const float d0 = __fdividef(1.f, __logf((float)(c0 + 2)));
    const float d1 = __fdividef(1.f, __logf((float)(c1 + 2)));
    const float g0 = 2.f * r0 - 1.f;
    const float g1 = 2.f * r1 - 1.f;
    const float sL0 = s0 * LOG2E;   // lg2-domain score
    const float sL1 = s1 * LOG2E;

    // interleaved tables: entry m serves pair (m,.) and the (m+32)-side pair
    Ptab[warp][lane]      = make_float4(sL0, sL1, g0, g1);
    Ptab[warp][lane + 32] = make_float4(sL1, sL0, g1, g0);
    Qtab[warp][lane]      = make_float2(d0, d1);
    Qtab[warp][lane + 32] = make_float2(d1, d0);
    __syncwarp();

    const float4* Pb = &Ptab[warp][lane];
    const float2* Qb = &Qtab[warp][lane];

    float acc0 = 0.f;   // pair-A softplus_lg2 terms
    float acc1 = 0.f;   // pair-B unoriented softplus_lg2 terms
    float accC = 0.f;   // pair-B wrapped correction: sum delta*x (lg2 domain)

    // Literal-K iteration: immediate-offset LDS, static predicate threshold.
    // Pair A = (lane, lane+K): partner idx > own -> oriented as-is.
    // Pair B = (lane+32, (lane+32+K)&63): wrapped (partner < own) iff lane+K>=32;
    // oriented value = lB - xB, folded via accC.
    #define PAIR_ITER(K) do {                                              \
        const float4 A = Pb[(K)];  /* {sL[m], sL[m'], g[m], g[m']} */      \
        const float2 D = Qb[(K)];  /* {d[m], d[m']} */                     \
        const float xA  = A.x - sL0;                                       \
        const float xB  = A.y - sL1;                                       \
        const float dtA = (A.z - g0) * (D.x - d0);                         \
        const float dtB = (A.w - g1) * (D.y - d1);                         \
        acc0 = fmaf(dtA, lg2f(1.f + ex2f(xA)), acc0);                      \
        acc1 = fmaf(dtB, lg2f(1.f + ex2f(xB)), acc1);                      \
        if (lane + (K) >= 32) accC = fmaf(dtB, xB, accC);                  \
    } while (0)

    PAIR_ITER(1);  PAIR_ITER(2);  PAIR_ITER(3);  PAIR_ITER(4);
    PAIR_ITER(5);  PAIR_ITER(6);  PAIR_ITER(7);  PAIR_ITER(8);
    PAIR_ITER(9);  PAIR_ITER(10); PAIR_ITER(11); PAIR_ITER(12);
    PAIR_ITER(13); PAIR_ITER(14); PAIR_ITER(15); PAIR_ITER(16);
    PAIR_ITER(17); PAIR_ITER(18); PAIR_ITER(19); PAIR_ITER(20);
    PAIR_ITER(21); PAIR_ITER(22); PAIR_ITER(23); PAIR_ITER(24);
    PAIR_ITER(25); PAIR_ITER(26); PAIR_ITER(27); PAIR_ITER(28);
    PAIR_ITER(29); PAIR_ITER(30); PAIR_ITER(31);
    #undef PAIR_ITER

    {   // gap-32 pair (lane, lane+32): i = lane+32 > j = lane
        const float delta = (g1 - g0) * (d1 - d0);   // >= 0
        acc0 = fmaf(delta, lg2f(1.f + ex2f(sL1 - sL0)), acc0);
    }
    float acc = (acc0 + acc1 - accC) * LN2;

    // ---- warp reduce ----
    #pragma unroll
    for (int o = 16; o; o >>= 1)
        acc += __shfl_xor_sync(0xffffffffu, acc, o);
    if (lane == 0) wsum[warp] = acc;
    __syncthreads();

    if (threadIdx.x == 0) {
        float s = 0.f;
        #pragma unroll
        for (int w = 0; w < ROWS_PER_BLOCK; w++) s += wsum[w];
        g_partials[blockIdx.x] = s;
        __threadfence();
        const unsigned tk = atomicAdd(&g_ticket, 1u);
        isLast = (tk == (unsigned)(gridDim.x - 1));
    }
    __syncthreads();

    // ---- last block: deterministic fixed-order reduction of 1024 partials ----
    if (isLast) {
        const int tid = threadIdx.x;
        float v = g_partials[tid]
                + g_partials[tid + 256]
                + g_partials[tid + 512]
                + g_partials[tid + 768];
        red[tid] = v;
        __syncthreads();
        #pragma unroll
        for (int stride = THREADS / 2; stride > 0; stride >>= 1) {
            if (tid < stride) red[tid] += red[tid + stride];
            __syncthreads();
        }
        if (tid == 0) {
            out[0] = red[0] * INV_PAIR_COUNT;
            g_ticket = 0;   // reset for graph replay
        }
    }
}

extern "C" void kernel_launch(void* const* d_in, const int* in_sizes, int n_in,
                              void* d_out, int out_size) {
    (void)in_sizes; (void)n_in; (void)out_size;
    const float* s = (const float*)d_in[0];   // policy_logps
    const float* r = (const float*)d_in[1];   // reward_scores
    rankdpo_fused<<<NUM_BLOCKS, THREADS>>>(s, r, (float*)d_out);
}

// round 10
// speedup vs baseline: 1.0803x; 1.0785x over previous
#include <cuda_runtime.h>

// RankDPO loss, B=8192, K=64. Single fused kernel.
// R10: co-bound issue+MUFU model -> halve the EX2 count via ex2.approx.f16x2
// (one MUFU op serves both pairs of an iteration); 1+t and the accumulate run
// packed (add/fma.rn.f32x2). lg2 stays f32 (no f16 lg2 exists).
// Math: delta = (g_i-g_j)*(d_i-d_j) >= 0 (monotone in r, no abs);
// softplus in lg2 domain; wrapped pair-B orientation via correction
// accumulator using softplus(-x) = softplus(x) - x.

#define ROWS_PER_BLOCK 8
#define THREADS 256
#define NUM_BLOCKS 1024                      // 8192 / 8
#define INV_PAIR_COUNT (1.0f / 16515072.0f)  // 8192 * 2016
#define LOG2E 1.4426950408889634f
#define LN2   0.6931471805599453f

static __device__ float g_partials[NUM_BLOCKS];
static __device__ unsigned int g_ticket = 0;

typedef unsigned long long u64;

static __device__ __forceinline__ float lg2f(float x) {
    float y; asm("lg2.approx.f32 %0, %1;" : "=f"(y) : "f"(x)); return y;
}
static __device__ __forceinline__ float ex2f(float x) {
    float y; asm("ex2.approx.f32 %0, %1;" : "=f"(y) : "f"(x)); return y;
}
static __device__ __forceinline__ u64 packf2(float lo, float hi) {
    u64 r; asm("mov.b64 %0, {%1, %2};" : "=l"(r) : "f"(lo), "f"(hi)); return r;
}
static __device__ __forceinline__ void unpackf2(float& lo, float& hi, u64 v) {
    asm("mov.b64 {%0, %1}, %2;" : "=f"(lo), "=f"(hi) : "l"(v));
}
static __device__ __forceinline__ u64 addx2(u64 a, u64 b) {
    u64 r; asm("add.rn.f32x2 %0, %1, %2;" : "=l"(r) : "l"(a), "l"(b)); return r;
}
static __device__ __forceinline__ u64 mulx2(u64 a, u64 b) {
    u64 r; asm("mul.rn.f32x2 %0, %1, %2;" : "=l"(r) : "l"(a), "l"(b)); return r;
}
static __device__ __forceinline__ u64 fmax2(u64 a, u64 b, u64 c) {
    u64 r; asm("fma.rn.f32x2 %0, %1, %2, %3;" : "=l"(r) : "l"(a), "l"(b), "l"(c)); return r;
}
// t = {2^xA, 2^xB} computed through f16x2 (ONE MUFU op), results back as f32
static __device__ __forceinline__ void ex2_pair_f16(float xA, float xB,
                                                   float& tA, float& tB) {
    unsigned h, t;
    asm("cvt.rn.f16x2.f32 %0, %1, %2;" : "=r"(h) : "f"(xB), "f"(xA)); // lo=xA
    asm("ex2.approx.f16x2 %0, %1;" : "=r"(t) : "r"(h));
    asm("{ .reg .b16 lo, hi;\n\t"
        "  mov.b32 {lo, hi}, %2;\n\t"
        "  cvt.f32.f16 %0, lo;\n\t"
        "  cvt.f32.f16 %1, hi; }"
        : "=f"(tA), "=f"(tB) : "r"(t));
}

__global__ __launch_bounds__(THREADS)
void rankdpo_fused(const float* __restrict__ S,
                   const float* __restrict__ R,
                   float* __restrict__ out) {
    __shared__ __align__(16) float4 Ptab[ROWS_PER_BLOCK][64];
    __shared__ __align__(8)  float2 Qtab[ROWS_PER_BLOCK][64];
    __shared__ __align__(16) float  rsh[ROWS_PER_BLOCK][64];
    __shared__ float wsum[ROWS_PER_BLOCK];
    __shared__ float red[THREADS];
    __shared__ int   isLast;

    const int warp = threadIdx.x >> 5;
    const int lane = threadIdx.x & 31;
    const int row  = blockIdx.x * ROWS_PER_BLOCK + warp;

    const float* srow = S + row * 64;
    const float* rrow = R + row * 64;
    const float s0 = srow[lane];
    const float s1 = srow[lane + 32];
    const float r0 = rrow[lane];
    const float r1 = rrow[lane + 32];

    float* rw = rsh[warp];
    rw[lane]      = r0;
    rw[lane + 32] = r1;
    __syncwarp();

    // ---- rank: count strictly-greater rewards (ties ~2^-23/pair; tied pairs
    //      have dg=0 -> delta=0, so dropped tie-break is harmless) ----
    int c0 = 0, c1 = 0;
    const float4* rv = (const float4*)rw;
    #pragma unroll
    for (int q = 0; q < 16; q++) {
        const float4 v = rv[q];
        c0 += (v.x > r0) + (v.y > r0) + (v.z > r0) + (v.w > r0);
        c1 += (v.x > r1) + (v.y > r1) + (v.z > r1) + (v.w > r1);
    }
    const float d0 = __fdividef(1.f, __logf((float)(c0 + 2)));
    const float d1 = __fdividef(1.f, __logf((float)(c1 + 2)));
    const float g0 = 2.f * r0 - 1.f;
    const float g1 = 2.f * r1 - 1.f;
    const float sL0 = s0 * LOG2E;   // lg2-domain score
    const float sL1 = s1 * LOG2E;

    // interleaved tables: entry m serves pair (m,.) and the (m+32)-side pair
    Ptab[warp][lane]      = make_float4(sL0, sL1, g0, g1);
    Ptab[warp][lane + 32] = make_float4(sL1, sL0, g1, g0);
    Qtab[warp][lane]      = make_float2(d0, d1);
    Qtab[warp][lane + 32] = make_float2(d1, d0);
    __syncwarp();

    const u64 negS2 = packf2(-sL0, -sL1);
    const u64 negG2 = packf2(-g0, -g1);
    const u64 negD2 = packf2(-d0, -d1);
    const u64 one2  = packf2(1.f, 1.f);

    const float4* Pb = &Ptab[warp][lane];
    const float2* Qb = &Qtab[warp][lane];

    u64   acc2 = 0;     // packed {accA, accB}: delta * lg2(1+2^x) sums
    float accC = 0.f;   // pair-B wrapped correction: sum delta*x (lg2 domain)
    #pragma unroll
    for (int k = 1; k < 32; k++) {
        const u64* pv = (const u64*)(Pb + k);
        const u64 sP = pv[0];                 // {sL[m], sL[(m+32)&63]}
        const u64 gP = pv[1];                 // {g[m],  g[(m+32)&63]}
        const u64 dP = *(const u64*)(Qb + k); // {d[m],  d[(m+32)&63]}

        const u64 x2     = addx2(sP, negS2);  // s_partner - s_own (lg2 dom)
        const u64 dg2    = addx2(gP, negG2);
        const u64 dd2    = addx2(dP, negD2);
        const u64 delta2 = mulx2(dg2, dd2);   // >= 0 by monotonicity, no abs

        float xA, xB;
        unpackf2(xA, xB, x2);

        // ONE f16x2 MUFU op computes both 2^x values
        float tA, tB;
        ex2_pair_f16(xA, xB, tA, tB);

        // packed 1+t, then two scalar lg2 (no f16 lg2 exists)
        float uA, uB;
        unpackf2(uA, uB, addx2(packf2(tA, tB), one2));
        const float lA = lg2f(uA);
        const float lB = lg2f(uB);

        // packed accumulate of both pair terms
        acc2 = fmax2(delta2, packf2(lA, lB), acc2);

        // pair B wrapped (lane+k>=32 -> partner < own): oriented = lB - xB
        if (lane + k >= 32) {
            float dtA, dtB;
            unpackf2(dtA, dtB, delta2);
            accC = fmaf(dtB, xB, accC);
        }
    }
    float accA, accB;
    unpackf2(accA, accB, acc2);
    {   // gap-32 pair (lane, lane+32): i = lane+32 > j = lane (exact f32 path)
        const float delta = (g1 - g0) * (d1 - d0);   // >= 0
        accA = fmaf(delta, lg2f(1.f + ex2f(sL1 - sL0)), accA);
    }
    float acc = (accA + accB - accC) * LN2;

    // ---- warp reduce ----
    #pragma unroll
    for (int o = 16; o; o >>= 1)
        acc += __shfl_xor_sync(0xffffffffu, acc, o);
    if (lane == 0) wsum[warp] = acc;
    __syncthreads();

    if (threadIdx.x == 0) {
        float s = 0.f;
        #pragma unroll
        for (int w = 0; w < ROWS_PER_BLOCK; w++) s += wsum[w];
        g_partials[blockIdx.x] = s;
        __threadfence();
        const unsigned tk = atomicAdd(&g_ticket, 1u);
        isLast = (tk == (unsigned)(gridDim.x - 1));
    }
    __syncthreads();

    // ---- last block: deterministic fixed-order reduction of 1024 partials ----
    if (isLast) {
        const int tid = threadIdx.x;
        float v = g_partials[tid]
                + g_partials[tid + 256]
                + g_partials[tid + 512]
                + g_partials[tid + 768];
        red[tid] = v;
        __syncthreads();
        #pragma unroll
        for (int stride = THREADS / 2; stride > 0; stride >>= 1) {
            if (tid < stride) red[tid] += red[tid + stride];
            __syncthreads();
        }
        if (tid == 0) {
            out[0] = red[0] * INV_PAIR_COUNT;
            g_ticket = 0;   // reset for graph replay
        }
    }
}

extern "C" void kernel_launch(void* const* d_in, const int* in_sizes, int n_in,
                              void* d_out, int out_size) {
    (void)in_sizes; (void)n_in; (void)out_size;
    const float* s = (const float*)d_in[0];   // policy_logps
    const float* r = (const float*)d_in[1];   // reward_scores
    rankdpo_fused<<<NUM_BLOCKS, THREADS>>>(s, r, (float*)d_out);
}

// round 11
// speedup vs baseline: 1.1233x; 1.0398x over previous
#include <cuda_runtime.h>

// RankDPO loss, B=8192, K=64. Single fused kernel (R6 structure refined).
// Packed f32x2 ONLY on the LDS-fed producer side (operands arrive in aligned
// register pairs -> zero MOV glue); scalar consumers (EX2/LG2/FFMA) read the
// pair halves directly. LN2 scaling postponed to the final scalar.
// Math: delta = (g_i-g_j)*(d_i-d_j) >= 0 (monotone in r, no abs);
// softplus in lg2 domain; wrapped pair-B orientation via correction
// accumulator using softplus(-x) = softplus(x) - x.

#define ROWS_PER_BLOCK 8
#define THREADS 256
#define NUM_BLOCKS 1024                      // 8192 / 8
#define LOG2E 1.4426950408889634f
#define LN2   0.6931471805599453f
#define FINAL_SCALE (LN2 / 16515072.0f)      // ln2 / (8192 * 2016)

static __device__ float g_partials[NUM_BLOCKS];
static __device__ unsigned int g_ticket = 0;

typedef unsigned long long u64;

static __device__ __forceinline__ float ex2f(float x) {
    float y; asm("ex2.approx.f32 %0, %1;" : "=f"(y) : "f"(x)); return y;
}
static __device__ __forceinline__ float lg2f(float x) {
    float y; asm("lg2.approx.f32 %0, %1;" : "=f"(y) : "f"(x)); return y;
}
static __device__ __forceinline__ u64 packf2(float lo, float hi) {
    u64 r; asm("mov.b64 %0, {%1, %2};" : "=l"(r) : "f"(lo), "f"(hi)); return r;
}
static __device__ __forceinline__ void unpackf2(float& lo, float& hi, u64 v) {
    asm("mov.b64 {%0, %1}, %2;" : "=f"(lo), "=f"(hi) : "l"(v));
}
static __device__ __forceinline__ u64 addx2(u64 a, u64 b) {
    u64 r; asm("add.rn.f32x2 %0, %1, %2;" : "=l"(r) : "l"(a), "l"(b)); return r;
}
static __device__ __forceinline__ u64 mulx2(u64 a, u64 b) {
    u64 r; asm("mul.rn.f32x2 %0, %1, %2;" : "=l"(r) : "l"(a), "l"(b)); return r;
}

__global__ __launch_bounds__(THREADS, 7)
void rankdpo_fused(const float* __restrict__ S,
                   const float* __restrict__ R,
                   float* __restrict__ out) {
    __shared__ __align__(16) float4 Ptab[ROWS_PER_BLOCK][64];
    __shared__ __align__(8)  float2 Qtab[ROWS_PER_BLOCK][64];
    __shared__ __align__(16) float  rsh[ROWS_PER_BLOCK][64];
    __shared__ float wsum[ROWS_PER_BLOCK];
    __shared__ float red[THREADS];
    __shared__ int   isLast;

    const int warp = threadIdx.x >> 5;
    const int lane = threadIdx.x & 31;
    const int row  = blockIdx.x * ROWS_PER_BLOCK + warp;

    const float* srow = S + row * 64;
    const float* rrow = R + row * 64;
    const float s0 = srow[lane];
    const float s1 = srow[lane + 32];
    const float r0 = rrow[lane];
    const float r1 = rrow[lane + 32];

    float* rw = rsh[warp];
    rw[lane]      = r0;
    rw[lane + 32] = r1;
    __syncwarp();

    // ---- rank: count strictly-greater rewards (ties ~2^-23/pair; tied pairs
    //      have dg=0 -> delta=0, so dropped tie-break is harmless) ----
    int c0 = 0, c1 = 0;
    const float4* rv = (const float4*)rw;
    #pragma unroll
    for (int q = 0; q < 16; q++) {
        const float4 v = rv[q];
        c0 += (v.x > r0) + (v.y > r0) + (v.z > r0) + (v.w > r0);
        c1 += (v.x > r1) + (v.y > r1) + (v.z > r1) + (v.w > r1);
    }
    const float d0 = __fdividef(1.f, __logf((float)(c0 + 2)));
    const float d1 = __fdividef(1.f, __logf((float)(c1 + 2)));
    const float g0 = 2.f * r0 - 1.f;
    const float g1 = 2.f * r1 - 1.f;
    const float sL0 = s0 * LOG2E;   // lg2-domain score
    const float sL1 = s1 * LOG2E;

    // interleaved tables: entry m serves pair (m,.) and the (m+32)-side pair
    Ptab[warp][lane]      = make_float4(sL0, sL1, g0, g1);
    Ptab[warp][lane + 32] = make_float4(sL1, sL0, g1, g0);
    Qtab[warp][lane]      = make_float2(d0, d1);
    Qtab[warp][lane + 32] = make_float2(d1, d0);
    __syncwarp();

    const u64 negS2 = packf2(-sL0, -sL1);
    const u64 negG2 = packf2(-g0, -g1);
    const u64 negD2 = packf2(-d0, -d1);

    const float4* Pb = &Ptab[warp][lane];
    const float2* Qb = &Qtab[warp][lane];

    float acc0 = 0.f;   // pair-A softplus_lg2 terms
    float acc1 = 0.f;   // pair-B unoriented softplus_lg2 terms
    float accC = 0.f;   // pair-B wrapped correction: sum delta*x (lg2 domain)
    #pragma unroll
    for (int k = 1; k < 32; k++) {
        const u64* pv = (const u64*)(Pb + k);
        const u64 sP = pv[0];                 // {sL[m], sL[(m+32)&63]}
        const u64 gP = pv[1];                 // {g[m],  g[(m+32)&63]}
        const u64 dP = *(const u64*)(Qb + k); // {d[m],  d[(m+32)&63]}

        // packed producers: all operands are naturally-aligned register pairs
        const u64 x2     = addx2(sP, negS2);  // s_partner - s_own (lg2 dom)
        const u64 dg2    = addx2(gP, negG2);
        const u64 dd2    = addx2(dP, negD2);
        const u64 delta2 = mulx2(dg2, dd2);   // >= 0 by monotonicity, no abs

        // scalar consumers read the pair halves directly (no repack)
        float xA, xB, dtA, dtB;
        unpackf2(xA, xB, x2);
        unpackf2(dtA, dtB, delta2);

        // pair A: partner index lane+k > lane always -> oriented as-is
        acc0 = fmaf(dtA, lg2f(1.f + ex2f(xA)), acc0);

        // pair B: unoriented softplus; wrapped (lane+k>=32 -> partner < own):
        // oriented value = lB - xB, folded via correction accumulator
        acc1 = fmaf(dtB, lg2f(1.f + ex2f(xB)), acc1);
        if (lane + k >= 32) accC = fmaf(dtB, xB, accC);
    }
    {   // gap-32 pair (lane, lane+32): i = lane+32 > j = lane
        const float delta = (g1 - g0) * (d1 - d0);   // >= 0
        acc0 = fmaf(delta, lg2f(1.f + ex2f(sL1 - sL0)), acc0);
    }
    float acc = acc0 + acc1 - accC;   // lg2 domain; ln2 folded into FINAL_SCALE

    // ---- warp reduce ----
    #pragma unroll
    for (int o = 16; o; o >>= 1)
        acc += __shfl_xor_sync(0xffffffffu, acc, o);
    if (lane == 0) wsum[warp] = acc;
    __syncthreads();

    if (threadIdx.x == 0) {
        float s = 0.f;
        #pragma unroll
        for (int w = 0; w < ROWS_PER_BLOCK; w++) s += wsum[w];
        g_partials[blockIdx.x] = s;
        __threadfence();
        const unsigned tk = atomicAdd(&g_ticket, 1u);
        isLast = (tk == (unsigned)(gridDim.x - 1));
    }
    __syncthreads();

    // ---- last block: deterministic fixed-order reduction of 1024 partials ----
    if (isLast) {
        const int tid = threadIdx.x;
        float v = g_partials[tid]
                + g_partials[tid + 256]
                + g_partials[tid + 512]
                + g_partials[tid + 768];
        red[tid] = v;
        __syncthreads();
        #pragma unroll
        for (int stride = THREADS / 2; stride > 0; stride >>= 1) {
            if (tid < stride) red[tid] += red[tid + stride];
            __syncthreads();
        }
        if (tid == 0) {
            out[0] = red[0] * FINAL_SCALE;
            g_ticket = 0;   // reset for graph replay
        }
    }
}

extern "C" void kernel_launch(void* const* d_in, const int* in_sizes, int n_in,
                              void* d_out, int out_size) {
    (void)in_sizes; (void)n_in; (void)out_size;
    const float* s = (const float*)d_in[0];   // policy_logps
    const float* r = (const float*)d_in[1];   // reward_scores
    rankdpo_fused<<<NUM_BLOCKS, THREADS>>>(s, r, (float*)d_out);
}